// round 11
// baseline (speedup 1.0000x reference)
#include <cuda_runtime.h>
#include <cuda_bf16.h>
#include <stdint.h>
#include <math.h>

#define Bn 128
#define Ln 1024
#define Vn 32
#define En 256
#define Hn 1024
#define NTOT 1056        // Hn + Vn (W_o folded)

#define NG  4            // independent batch groups
#define BG  32           // batch rows per group
#define NTL 33           // CTAs per group (32 h-tiles + 1 logits tile)
#define NSL 32           // N cols per CTA
#define G   (NG * NTL)   // 132 persistent CTAs
#define NT  512          // 16 warps: (kf 0..7) x (nh 0..1)
#define KW  128          // K columns per k-slice
#define PA  1032         // A/B smem pitch (bf16): 2064B stride -> LDSM conflict-free
#define PN  36           // reduction pitch (floats)

// ---------------- device scratch ----------------
__device__ float         g_P[Vn * Hn];
__device__ __nv_bfloat16 g_hbf_hi[2][Bn * Hn];
__device__ __nv_bfloat16 g_hbf_lo[2][Bn * Hn];
__device__ __nv_bfloat16 g_WT_hi[NTOT * Hn];   // [n][k]
__device__ __nv_bfloat16 g_WT_lo[NTOT * Hn];
__device__ unsigned      g_cnt_all;            // prologue barrier (all G)
__device__ unsigned      g_cntg[NG * 8];       // per-group step counters (padded)

// smem layout (bytes)
#define OFF_ALO 66048                          // 32*PA*2
#define OFF_RED 132096
#define OFF_X   168960                         // 132096 + 8*32*PN*4
#define SMEM_BYTES 169088
#define A_MT (16 * PA * 2)                     // byte offset between m-tiles

// ---------------- helpers ----------------
#define MMA16816(d, a0, a1, a2, a3, b0, b1) \
    asm volatile("mma.sync.aligned.m16n8k16.row.col.f32.bf16.bf16.f32 " \
        "{%0,%1,%2,%3}, {%4,%5,%6,%7}, {%8,%9}, {%0,%1,%2,%3};" \
        : "+f"((d)[0]), "+f"((d)[1]), "+f"((d)[2]), "+f"((d)[3]) \
        : "r"(a0), "r"(a1), "r"(a2), "r"(a3), "r"(b0), "r"(b1))

#define LDSM4(r0, r1, r2, r3, addr) \
    asm volatile("ldmatrix.sync.aligned.m8n8.x4.shared.b16 {%0,%1,%2,%3}, [%4];" \
        : "=r"(r0), "=r"(r1), "=r"(r2), "=r"(r3) : "r"(addr))

__device__ __forceinline__ uint32_t smem_u32(const void* p) {
    uint32_t a;
    asm("{ .reg .u64 t; cvta.to.shared.u64 t, %1; cvt.u32.u64 %0, t; }"
        : "=r"(a) : "l"(p));
    return a;
}
__device__ __forceinline__ unsigned acqload(const unsigned* p) {
    unsigned v;
    asm volatile("ld.acquire.gpu.u32 %0, [%1];" : "=r"(v) : "l"(p) : "memory");
    return v;
}
__device__ __forceinline__ void arrive(unsigned* cnt) {
    asm volatile("red.release.gpu.global.add.u32 [%0], 1;" :: "l"(cnt) : "memory");
}
__device__ __forceinline__ void waitcnt(unsigned* cnt, unsigned target) {
    unsigned v = acqload(cnt);
    while ((int)(v - target) < 0) v = acqload(cnt);
}
__device__ __forceinline__ uint4 ldcg4(const void* p) {
    uint4 r;
    asm volatile("ld.global.cg.v4.u32 {%0,%1,%2,%3}, [%4];"
        : "=r"(r.x), "=r"(r.y), "=r"(r.z), "=r"(r.w) : "l"(p));
    return r;
}
__device__ __forceinline__ void pack_hilo(float v, unsigned short& hi, unsigned short& lo) {
    __nv_bfloat16 hb = __float2bfloat16(v);
    hi = __bfloat16_as_ushort(hb);
    lo = __bfloat16_as_ushort(__float2bfloat16(v - __bfloat162float(hb)));
}
__device__ __forceinline__ float fast_tanh(float x) {
    float e = __expf(2.0f * x);
    return 1.0f - __fdividef(2.0f, e + 1.0f);
}

// ---------------- the single persistent kernel ----------------
__global__ void __launch_bounds__(NT, 1)
rnn_all(const int* __restrict__ x, const float* __restrict__ hidden,
        const float* __restrict__ emb, const float* __restrict__ We,
        const float* __restrict__ Wh, const float* __restrict__ bh,
        const float* __restrict__ Wo, const float* __restrict__ bo,
        float* __restrict__ logits, float* __restrict__ outh) {
    extern __shared__ __align__(16) char dsm[];
    __nv_bfloat16* sAhi = (__nv_bfloat16*)dsm;
    __nv_bfloat16* sAlo = (__nv_bfloat16*)(dsm + OFF_ALO);
    float*         sRed = (float*)(dsm + OFF_RED);
    int*           sX   = (int*)(dsm + OFF_X);

    const int tid = threadIdx.x, bid = blockIdx.x;
    const int g     = bid / NTL;        // batch group 0..3
    const int ntl   = bid % NTL;        // 0..32 (32 = logits tile)
    const int gbase = g * BG;
    const int ncol0 = ntl * NSL;        // global N col base (1024 = logits)
    const int lane = tid & 31, w = tid >> 5;
    const int kf = w >> 1;              // k-slice 0..7 (128 wide)
    const int nh = w & 1;               // n-half (16 cols)
    const int gq = lane >> 2, tg = lane & 3;

    unsigned tokA = acqload(&g_cnt_all);
    unsigned tokG = acqload(&g_cntg[g * 8]);

    // ======== prologue ========
    for (int k2 = tid; k2 < Hn; k2 += NT) {
#pragma unroll
        for (int j = 0; j < 8; ++j) {
            int n = bid * 8 + j;
            float wv = (n < Hn) ? Wh[k2 * Hn + n] : Wo[k2 * Vn + (n - Hn)];
            unsigned short hi, lo; pack_hilo(wv, hi, lo);
            g_WT_hi[n * Hn + k2] = __ushort_as_bfloat16(hi);
            g_WT_lo[n * Hn + k2] = __ushort_as_bfloat16(lo);
        }
    }
    {
        int e = bid * NT + tid;
        if (e < Vn * Hn) {
            int v = e >> 10, h = e & 1023;
            float acc = bh[h];
            const float* er = emb + v * En;
#pragma unroll 8
            for (int q = 0; q < En; ++q) acc = fmaf(er[q], We[q * Hn + h], acc);
            g_P[e] = acc;
        }
    }
    if (bid < Bn) {
        int i0 = bid * Hn + tid * 2;
        float2 hv = *(const float2*)(hidden + i0);
        unsigned short h0u, l0u, h1u, l1u;
        pack_hilo(hv.x, h0u, l0u); pack_hilo(hv.y, h1u, l1u);
        *(uint32_t*)(&g_hbf_hi[0][i0]) = (uint32_t)h0u | ((uint32_t)h1u << 16);
        *(uint32_t*)(&g_hbf_lo[0][i0]) = (uint32_t)l0u | ((uint32_t)l1u << 16);
    }
    __syncthreads();
    if (tid == 0) arrive(&g_cnt_all);
    tokA += G;
    if (tid == 0) waitcnt(&g_cnt_all, tokA);
    __syncthreads();

    // ======== B setup: stage tile once, LDSM fragments into registers ========
    uint32_t Bh[8][2][2], Bl[8][2][2];
    {
#pragma unroll
        for (int it = 0; it < 8; ++it) {
            int i = (it * NT + tid) * 8;
            int n = i >> 10, k = i & 1023;
            *(uint4*)(sAhi + n * PA + k) = *(const uint4*)(&g_WT_hi[(ncol0 + n) * Hn + k]);
            *(uint4*)(sAlo + n * PA + k) = *(const uint4*)(&g_WT_lo[(ncol0 + n) * Hn + k]);
        }
        __syncthreads();
        const uint32_t ba = smem_u32(sAhi) +
            (uint32_t)(2 * ((nh * 16 + (lane >> 4) * 8 + (lane & 7)) * PA
                            + kf * KW + ((lane >> 3) & 1) * 8));
#pragma unroll
        for (int s = 0; s < 8; ++s) {
            LDSM4(Bh[s][0][0], Bh[s][0][1], Bh[s][1][0], Bh[s][1][1], ba + s * 32);
            LDSM4(Bl[s][0][0], Bl[s][0][1], Bl[s][1][0], Bl[s][1][1],
                  ba + s * 32 + (uint32_t)OFF_ALO);
        }
        __syncthreads();
    }

    const uint32_t aBase = smem_u32(sAhi) +
        (uint32_t)(2 * (((lane & 7) + ((lane >> 3) & 1) * 8) * PA
                        + kf * KW + (lane >> 4) * 8));

    // ======== recurrence ========
    for (int l = 0; l <= Ln; ++l) {
        const int c = l & 1;
        const bool act = (l < Ln) || (ntl == NTL - 1);

        float acc[2][2][4];
#pragma unroll
        for (int mt = 0; mt < 2; ++mt)
#pragma unroll
            for (int nb = 0; nb < 2; ++nb)
#pragma unroll
                for (int q = 0; q < 4; ++q) acc[mt][nb][q] = 0.f;

        if (act) {   // stage A-hi
#pragma unroll
            for (int it = 0; it < 8; ++it) {
                int i = (it * NT + tid) * 8;
                int row = i >> 10, k = i & 1023;
                *(uint4*)(sAhi + row * PA + k) = ldcg4(&g_hbf_hi[c][(gbase + row) * Hn + k]);
            }
            if (l < Ln && tid < BG) sX[tid] = __ldg(&x[(gbase + tid) * Ln + l]);
        }
        __syncthreads();

        if (act) {
            auto mma_hi = [&]() {
#pragma unroll
                for (int mt = 0; mt < 2; ++mt) {
                    const uint32_t mo = (uint32_t)(mt * A_MT);
#pragma unroll
                    for (int s = 0; s < 8; ++s) {
                        uint32_t a0, a1, a2, a3;
                        LDSM4(a0, a1, a2, a3, aBase + mo + s * 32);
#pragma unroll
                        for (int nb = 0; nb < 2; ++nb) {
                            MMA16816(acc[mt][nb], a0, a1, a2, a3, Bh[s][nb][0], Bh[s][nb][1]);
                            MMA16816(acc[mt][nb], a0, a1, a2, a3, Bl[s][nb][0], Bl[s][nb][1]);
                        }
                    }
                }
            };
            auto stage_lo = [&]() {
#pragma unroll
                for (int it = 0; it < 8; ++it) {
                    int i = (it * NT + tid) * 8;
                    int row = i >> 10, k = i & 1023;
                    *(uint4*)(sAlo + row * PA + k) =
                        ldcg4(&g_hbf_lo[c][(gbase + row) * Hn + k]);
                }
            };
            if (nh) { mma_hi(); stage_lo(); }
            else    { stage_lo(); mma_hi(); }
        }
        __syncthreads();

        if (act) {
            // lo term: Alo x Bhi
#pragma unroll
            for (int mt = 0; mt < 2; ++mt) {
                const uint32_t mo = (uint32_t)(mt * A_MT);
#pragma unroll
                for (int s = 0; s < 8; ++s) {
                    uint32_t a0, a1, a2, a3;
                    LDSM4(a0, a1, a2, a3, aBase + (uint32_t)OFF_ALO + mo + s * 32);
#pragma unroll
                    for (int nb = 0; nb < 2; ++nb)
                        MMA16816(acc[mt][nb], a0, a1, a2, a3, Bh[s][nb][0], Bh[s][nb][1]);
                }
            }
            // per-k-slice partials
            float* rp = sRed + kf * 32 * PN;
#pragma unroll
            for (int mt = 0; mt < 2; ++mt)
#pragma unroll
                for (int nb = 0; nb < 2; ++nb) {
                    int r0 = mt * 16 + gq, col = nh * 16 + nb * 8 + tg * 2;
                    *(float2*)(rp + r0 * PN + col)       = make_float2(acc[mt][nb][0], acc[mt][nb][1]);
                    *(float2*)(rp + (r0 + 8) * PN + col) = make_float2(acc[mt][nb][2], acc[mt][nb][3]);
                }
        }
        __syncthreads();

        if (act) {
            // reduce 8 k-slices: thread owns (row m, 2 cols)
            const int m = tid >> 4, n0 = (tid & 15) * 2;
            float2 s = *(const float2*)(sRed + m * PN + n0);
#pragma unroll
            for (int j = 1; j < 8; ++j) {
                float2 p = *(const float2*)(sRed + j * 32 * PN + m * PN + n0);
                s.x += p.x; s.y += p.y;
            }
            if (ntl < NTL - 1) {
                if (l < Ln) {
                    const int xv = sX[m];
                    float2 Pv = *(const float2*)(&g_P[xv * Hn + ncol0 + n0]);
                    float h0 = fast_tanh(s.x + Pv.x), h1 = fast_tanh(s.y + Pv.y);
                    unsigned short h0u, l0u, h1u, l1u;
                    pack_hilo(h0, h0u, l0u); pack_hilo(h1, h1u, l1u);
                    int i0 = (gbase + m) * Hn + ncol0 + n0;
                    *(uint32_t*)(&g_hbf_hi[1 - c][i0]) = (uint32_t)h0u | ((uint32_t)h1u << 16);
                    *(uint32_t*)(&g_hbf_lo[1 - c][i0]) = (uint32_t)l0u | ((uint32_t)l1u << 16);
                    if (l == Ln - 1)
                        *(float2*)(&outh[i0]) = make_float2(h0, h1);
                }
            } else if (l > 0) {
                float2 B0 = *(const float2*)(&bo[n0]);
                *(float2*)(&logits[((size_t)(gbase + m) * Ln + (l - 1)) * Vn + n0]) =
                    make_float2(s.x + B0.x, s.y + B0.y);
            }
        }

        // per-group barrier (1 per step)
        if (l < Ln) {
            __syncthreads();
            if (tid == 0) arrive(&g_cntg[g * 8]);
            tokG += NTL;
            if (tid == 0) waitcnt(&g_cntg[g * 8], tokG);
            __syncthreads();
        }
    }
}

extern "C" void kernel_launch(void* const* d_in, const int* in_sizes, int n_in,
                              void* d_out, int out_size) {
    const int*   x      = (const int*)d_in[0];
    const float* hidden = (const float*)d_in[1];
    const float* emb    = (const float*)d_in[2];
    const float* We     = (const float*)d_in[3];
    const float* Wh     = (const float*)d_in[4];
    const float* bh     = (const float*)d_in[5];
    const float* Wo     = (const float*)d_in[6];
    const float* bo     = (const float*)d_in[7];

    float* logits = (float*)d_out;
    float* outh   = logits + (size_t)Bn * Ln * Vn;

    cudaFuncSetAttribute(rnn_all,
                         cudaFuncAttributeMaxDynamicSharedMemorySize, SMEM_BYTES);
    rnn_all<<<G, NT, SMEM_BYTES>>>(x, hidden, emb, We, Wh, bh, Wo, bo, logits, outh);
}